// round 11
// baseline (speedup 1.0000x reference)
#include <cuda_runtime.h>
#include <cuda_bf16.h>

#define PAD_VAL  -1000.0f
#define ROW      4096
#define NROWS    1024
#define SEGF     1024          // floats per segment
#define NSEG     4             // segments per row
#define NCHK     256           // owned 4-float chunks per segment
#define HALO     16            // halo chunks (next 64 floats)
#define RPB      4             // rows per block (per-thread ILP)
#define PLANE    (NCHK + HALO) // 272
#define THREADS  256

// out[i] = relu( max_{j=1..64} h[i+j]-j  -  h[i] ),  right-pad -1000.
// Segment-local frame G[t'] = h[t'] - t'  (t' <= 1087, all index constants
// fold away):   out[t'] = relu( max G[t'+1 .. t'+64] - G[t'] )
// Thread t owns chunk t (4 contiguous floats, coalesced float4) in 4 rows.
// Window = own suffix + whole chunks t+1..t+15 (chunk-max plane) + prefix of
// chunk t+16. Summary planes sP0..sP3 per row in smem (stride-1, conflict-
// free); chunk max = sP3. Front-batched 4 main + 1 halo LDG per thread.
__global__ __launch_bounds__(THREADS, 7) void h2i_kernel(
    const float* __restrict__ hf, float* __restrict__ out)
{
    const int t   = threadIdx.x;
    const int rg  = blockIdx.x >> 2;            // row group
    const int seg = blockIdx.x & (NSEG - 1);
    const size_t base0 = ((size_t)rg * RPB) * ROW + (size_t)seg * SEGF;

    __shared__ float sP0[RPB][PLANE];
    __shared__ float sP1[RPB][PLANE];
    __shared__ float sP2[RPB][PLANE];
    __shared__ float sP3[RPB][PLANE];

    // ---- front-batched loads: 4 main + (threads<64) 1 halo ----
    float4 a[RPB];
    #pragma unroll
    for (int j = 0; j < RPB; j++)
        a[j] = ((const float4*)(hf + base0 + (size_t)j * ROW))[t];

    float4 hr;
    const int hj = t >> 4, ht = t & 15;         // halo: row, chunk-in-halo
    if (t < 64) {
        if (seg < NSEG - 1)
            hr = ((const float4*)(hf + base0 + (size_t)hj * ROW + SEGF))[ht];
        else
            hr = make_float4(PAD_VAL, PAD_VAL, PAD_VAL, PAD_VAL);
    }

    // ---- reindex to G-frame + prefix maxes -> summary planes ----
    const float tb = (float)(4 * t);
    float g[RPB][4];
    #pragma unroll
    for (int j = 0; j < RPB; j++) {
        g[j][0] = a[j].x - tb;
        g[j][1] = a[j].y - (tb + 1.0f);
        g[j][2] = a[j].z - (tb + 2.0f);
        g[j][3] = a[j].w - (tb + 3.0f);
        const float p1 = fmaxf(g[j][0], g[j][1]);
        const float p2 = fmaxf(p1, g[j][2]);
        const float p3 = fmaxf(p2, g[j][3]);
        sP0[j][t] = g[j][0]; sP1[j][t] = p1; sP2[j][t] = p2; sP3[j][t] = p3;
    }
    if (t < 64) {
        const float hb = (float)(SEGF + 4 * ht);
        const float h0 = hr.x - hb,          h1 = hr.y - (hb + 1.0f);
        const float h2 = hr.z - (hb + 2.0f), h3 = hr.w - (hb + 3.0f);
        const float q1 = fmaxf(h0, h1), q2 = fmaxf(q1, h2), q3 = fmaxf(q2, h3);
        sP0[hj][NCHK + ht] = h0; sP1[hj][NCHK + ht] = q1;
        sP2[hj][NCHK + ht] = q2; sP3[hj][NCHK + ht] = q3;
    }
    __syncthreads();

    // ---- combine + store, 4 rows back-to-back (no index constants) ----
    #pragma unroll
    for (int j = 0; j < RPB; j++) {
        float mid = sP3[j][t + 1];
        #pragma unroll
        for (int k = 2; k <= 15; k++)
            mid = fmaxf(mid, sP3[j][t + k]);

        const float B0 = sP0[j][t + 16];
        const float B1 = sP1[j][t + 16];
        const float B2 = sP2[j][t + 16];
        const float B3 = sP3[j][t + 16];

        const float suf2 = g[j][3];
        const float suf1 = fmaxf(g[j][2], suf2);
        const float suf0 = fmaxf(g[j][1], suf1);

        float w, r0, r1, r2, r3;
        w = fmaxf(fmaxf(suf0, mid), B0); r0 = fmaxf(w - g[j][0], 0.0f);
        w = fmaxf(fmaxf(suf1, mid), B1); r1 = fmaxf(w - g[j][1], 0.0f);
        w = fmaxf(fmaxf(suf2, mid), B2); r2 = fmaxf(w - g[j][2], 0.0f);
        w = fmaxf(mid, B3);              r3 = fmaxf(w - g[j][3], 0.0f);

        ((float4*)(out + base0 + (size_t)j * ROW))[t] = make_float4(r0, r1, r2, r3);
    }
}

extern "C" void kernel_launch(void* const* d_in, const int* in_sizes, int n_in,
                              void* d_out, int out_size)
{
    const float* hf  = (const float*)d_in[0];
    float*       out = (float*)d_out;
    (void)in_sizes; (void)n_in; (void)out_size;
    // 7 blocks x 17.4KB smem per SM needs the max smem carveout.
    cudaFuncSetAttribute(h2i_kernel,
                         cudaFuncAttributePreferredSharedMemoryCarveout,
                         cudaSharedmemCarveoutMaxShared);
    // 256 row-groups x 4 segments = 1024 blocks; 7/SM -> single wave (1036)
    h2i_kernel<<<(NROWS / RPB) * NSEG, THREADS>>>(hf, out);
}